// round 15
// baseline (speedup 1.0000x reference)
#include <cuda_runtime.h>
#include <cuda_fp16.h>
#include <cstdint>

#define N_NODES 100000
#define E_EDGES 1600000
#define D 64

// Scratch (device globals: allocation-free per harness rules)
__device__ float  g_agg[(size_t)N_NODES * D];
__device__ float  g_buf[(size_t)N_NODES * D];
__device__ __half g_wh[7 * 4096];               // 7 pre-converted W^T fp16 planes
__device__ int    g_deg[N_NODES];
__device__ int    g_cur[N_NODES];
__device__ int    g_off[N_NODES];
__device__ int    g_srcs[E_EDGES];
__device__ int    g_part[128];
__device__ int    g_ei_is64;

struct WPtrs { const float* p[7]; };

// ===========================================================================
// zero + edge-index dtype probe + weight fp16 pre-conversion (one kernel)
// ===========================================================================
__global__ void zero_probe_wconv_kernel(const int* __restrict__ ei_i32, WPtrs ws) {
    __shared__ int nz;
    int t = threadIdx.x;
    int i = blockIdx.x * blockDim.x + t;
    if (i < N_NODES) { g_deg[i] = 0; g_cur[i] = 0; }
    if (blockIdx.x == 0) {
        if (t == 0) nz = 0;
        __syncthreads();
        if (t < 128 && ei_i32[2 * t + 1] != 0) atomicOr(&nz, 1);
        __syncthreads();
        if (t == 0) g_ei_is64 = (nz == 0) ? 1 : 0;
    } else if (blockIdx.x <= 7) {
        int m = blockIdx.x - 1;
        const float* w = ws.p[m];
        #pragma unroll 4
        for (int idx = t; idx < 4096; idx += 256) {
            int k = idx >> 6, n = idx & 63;      // w[k][n] -> wt[n][k]
            g_wh[m * 4096 + n * 64 + k] = __float2half_rn(__ldg(&w[idx]));
        }
    }
}

__device__ __forceinline__ int load_idx(const void* ei_raw, int pos) {
    if (g_ei_is64) return (int)__ldg(&((const long long*)ei_raw)[pos]);
    return __ldg(&((const int*)ei_raw)[pos]);
}

__global__ void hist_kernel(const void* __restrict__ ei_raw) {
    int e = blockIdx.x * blockDim.x + threadIdx.x;
    if (e >= E_EDGES) return;
    atomicAdd(&g_deg[load_idx(ei_raw, E_EDGES + e)], 1);
}

__global__ void __launch_bounds__(1024) scan1_kernel() {
    __shared__ int wsum[32];
    int i = blockIdx.x * 1024 + threadIdx.x;
    int v = (i < N_NODES) ? g_deg[i] : 0;
    int lane = threadIdx.x & 31, wid = threadIdx.x >> 5;
    int incl = v;
    #pragma unroll
    for (int d = 1; d < 32; d <<= 1) {
        int n = __shfl_up_sync(~0u, incl, d);
        if (lane >= d) incl += n;
    }
    if (lane == 31) wsum[wid] = incl;
    __syncthreads();
    if (wid == 0) {
        int s = wsum[lane];
        #pragma unroll
        for (int d = 1; d < 32; d <<= 1) {
            int n = __shfl_up_sync(~0u, s, d);
            if (lane >= d) s += n;
        }
        wsum[lane] = s;
    }
    __syncthreads();
    int woff = (wid > 0) ? wsum[wid - 1] : 0;
    if (i < N_NODES) g_off[i] = woff + incl - v;
    if (threadIdx.x == 1023) g_part[blockIdx.x] = woff + incl;
}

// Fused scan2+scan3
__global__ void __launch_bounds__(1024) scan23_kernel() {
    __shared__ int ssum[32];
    int t = threadIdx.x;
    int lane = t & 31, wid = t >> 5;
    int v = (t < blockIdx.x) ? g_part[t] : 0;
    #pragma unroll
    for (int d = 16; d >= 1; d >>= 1) v += __shfl_down_sync(~0u, v, d);
    if (lane == 0) ssum[wid] = v;
    __syncthreads();
    if (wid == 0) {
        int s = ssum[lane];
        #pragma unroll
        for (int d = 16; d >= 1; d >>= 1) s += __shfl_down_sync(~0u, s, d);
        if (lane == 0) ssum[0] = s;
    }
    __syncthreads();
    int add = ssum[0];
    int i = blockIdx.x * 1024 + t;
    if (i < N_NODES) g_off[i] += add;
}

__global__ void fill_kernel(const void* __restrict__ ei_raw) {
    int e = blockIdx.x * blockDim.x + threadIdx.x;
    if (e >= E_EDGES) return;
    int src = load_idx(ei_raw, e);
    int dst = load_idx(ei_raw, E_EDGES + e);
    g_srcs[g_off[dst] + atomicAdd(&g_cur[dst], 1)] = src;
}

// ===========================================================================
// agg[i] = x[i] + sum_{j in bucket(i)} x[srcs[j]]   (no atomics)
// ===========================================================================
__global__ void __launch_bounds__(256) aggregate_kernel(
    const float* __restrict__ x, float* __restrict__ agg)
{
    int node = blockIdx.x * 16 + (threadIdx.x >> 4);
    int c = threadIdx.x & 15;
    if (node >= N_NODES) return;

    int beg = __ldg(&g_off[node]);
    int cnt = __ldg(&g_deg[node]);
    float4 v = __ldg((const float4*)(x + (size_t)node * D) + c);

    int j = 0;
    for (; j + 2 <= cnt; j += 2) {
        int s0 = __ldg(&g_srcs[beg + j]);
        int s1 = __ldg(&g_srcs[beg + j + 1]);
        float4 u0 = __ldg((const float4*)(x + (size_t)s0 * D) + c);
        float4 u1 = __ldg((const float4*)(x + (size_t)s1 * D) + c);
        v.x += u0.x + u1.x; v.y += u0.y + u1.y;
        v.z += u0.z + u1.z; v.w += u0.w + u1.w;
    }
    if (j < cnt) {
        int s0 = __ldg(&g_srcs[beg + j]);
        float4 u0 = __ldg((const float4*)(x + (size_t)s0 * D) + c);
        v.x += u0.x; v.y += u0.y; v.z += u0.z; v.w += u0.w;
    }
    *((float4*)(agg + (size_t)node * D) + c) = v;
}

// ===========================================================================
// Tensor-core MLP via mma.sync.m16n8k16 FP16, 2-product split (R12 numerics).
// R15: (a) B fragments read DIRECTLY from gmem (fp16 W^T in g_wh; identical
//      addrs across CTAs -> L1 broadcast) -> smem 37.4KB -> 5 CTAs/SM
//      (grid 782 / 740 = 1.06 waves, was 1.32);
//      (b) packed split2 (cvt.rn.f16x2.f32) -> 40% less conversion ALU.
// CTA = 128 threads / 128 rows; warp w: rows 32w..32w+31, all 64 cols.
// ===========================================================================
#define SR 72

#define SM_BIAS1 0
#define SM_BIAS2 256
#define SM_AHI   512
#define SM_ALO   (SM_AHI + 128 * SR * 2)
#define SM_TOT   (SM_ALO + 128 * SR * 2)   // 37376 bytes

// packed split: (x0,x1) -> hi pair + lo pair (exact fp16 decomposition, rn)
__device__ __forceinline__ void split2(float x0, float x1,
                                       uint32_t& ph, uint32_t& pl) {
    __half2 h = __floats2half2_rn(x0, x1);        // 1 packed cvt
    float2 hf = __half22float2(h);                // 2 cvt
    __half2 l = __floats2half2_rn(x0 - hf.x, x1 - hf.y);  // 2 sub + 1 packed cvt
    ph = *(uint32_t*)&h;
    pl = *(uint32_t*)&l;
}

// NON-volatile: pure computation, lets the compiler schedule.
__device__ __forceinline__ void mma16816(float c[4], uint32_t a0, uint32_t a1,
                                         uint32_t a2, uint32_t a3,
                                         uint32_t b0, uint32_t b1) {
    asm("mma.sync.aligned.m16n8k16.row.col.f32.f16.f16.f32 "
        "{%0,%1,%2,%3}, {%4,%5,%6,%7}, {%8,%9}, {%0,%1,%2,%3};"
        : "+f"(c[0]), "+f"(c[1]), "+f"(c[2]), "+f"(c[3])
        : "r"(a0), "r"(a1), "r"(a2), "r"(a3), "r"(b0), "r"(b1));
}

__global__ void __launch_bounds__(128, 5) mlp_tc_kernel(
    const float* __restrict__ in, float* __restrict__ out,
    const __half* __restrict__ w1t, const float* __restrict__ b1,
    const __half* __restrict__ w2t, const float* __restrict__ b2,
    int two_layer)
{
    extern __shared__ char smem[];
    float* sB1f = (float*)(smem + SM_BIAS1);
    float* sB2f = (float*)(smem + SM_BIAS2);
    __half* sAhi = (__half*)(smem + SM_AHI);
    __half* sAlo = (__half*)(smem + SM_ALO);

    const int t = threadIdx.x;
    const int warp = t >> 5, lane = t & 31;
    const int g = lane >> 2, tig = lane & 3;
    const int m0 = warp * 32;
    const int row0 = blockIdx.x * 128;

    // per-thread B base: wt[n][k] with n = nt*8+g, k = k0+tig*2
    const __half* w1b = w1t + g * 64 + tig * 2;
    const __half* w2b = two_layer ? (w2t + g * 64 + tig * 2) : nullptr;

    // ---- stage A (hi/lo fp16 split, packed cvts): coalesced float4 reads ----
    #pragma unroll
    for (int i = 0; i < 16; i++) {
        int idx4 = t + i * 128;
        int r = idx4 >> 4, c4 = idx4 & 15;
        int gr = row0 + r;
        float4 v = make_float4(0.f, 0.f, 0.f, 0.f);
        if (gr < N_NODES) v = __ldg((const float4*)(in + (size_t)gr * D) + c4);
        uint32_t* ph = (uint32_t*)(sAhi + r * SR + c4 * 4);
        uint32_t* pl = (uint32_t*)(sAlo + r * SR + c4 * 4);
        split2(v.x, v.y, ph[0], pl[0]);
        split2(v.z, v.w, ph[1], pl[1]);
    }
    // ---- biases ----
    if (t < 16) ((float4*)sB1f)[t] = __ldg((const float4*)b1 + t);
    else if (t < 32 && two_layer) ((float4*)sB2f)[t - 16] = __ldg((const float4*)b2 + (t - 16));
    __syncthreads();   // the ONLY barrier

    float c[2][8][4];
    #pragma unroll
    for (int mt = 0; mt < 2; mt++)
        #pragma unroll
        for (int nt = 0; nt < 8; nt++)
            #pragma unroll
            for (int j = 0; j < 4; j++) c[mt][nt][j] = 0.f;

    // ---- layer-1 GEMM: A from smem, B frags from gmem (L1 broadcast) ----
    #pragma unroll
    for (int ks = 0; ks < 4; ks++) {
        const int k0 = ks * 16;
        uint32_t ah[2][4], al[2][4];
        #pragma unroll
        for (int mt = 0; mt < 2; mt++) {
            const __half* p0 = sAhi + (m0 + mt * 16 + g) * SR + k0 + tig * 2;
            const __half* q0 = sAlo + (m0 + mt * 16 + g) * SR + k0 + tig * 2;
            ah[mt][0] = *(const uint32_t*)p0;
            ah[mt][1] = *(const uint32_t*)(p0 + 8 * SR);
            ah[mt][2] = *(const uint32_t*)(p0 + 8);
            ah[mt][3] = *(const uint32_t*)(p0 + 8 * SR + 8);
            al[mt][0] = *(const uint32_t*)q0;
            al[mt][1] = *(const uint32_t*)(q0 + 8 * SR);
            al[mt][2] = *(const uint32_t*)(q0 + 8);
            al[mt][3] = *(const uint32_t*)(q0 + 8 * SR + 8);
        }
        #pragma unroll
        for (int nt = 0; nt < 8; nt++) {
            const __half* pb = w1b + nt * 512 + k0;
            uint32_t b0 = __ldg((const uint32_t*)pb);
            uint32_t b1 = __ldg((const uint32_t*)(pb + 8));
            mma16816(c[0][nt], ah[0][0], ah[0][1], ah[0][2], ah[0][3], b0, b1);
            mma16816(c[1][nt], ah[1][0], ah[1][1], ah[1][2], ah[1][3], b0, b1);
            mma16816(c[0][nt], al[0][0], al[0][1], al[0][2], al[0][3], b0, b1);
            mma16816(c[1][nt], al[1][0], al[1][1], al[1][2], al[1][3], b0, b1);
        }
    }

    if (two_layer) {
        // ---- h1 = relu(c + b1): packed split IN REGISTERS ----
        uint32_t phi[2][8][2], plo[2][8][2];
        #pragma unroll
        for (int mt = 0; mt < 2; mt++) {
            #pragma unroll
            for (int nt = 0; nt < 8; nt++) {
                int cb = nt * 8 + tig * 2;
                float o0 = fmaxf(c[mt][nt][0] + sB1f[cb],     0.f);
                float o1 = fmaxf(c[mt][nt][1] + sB1f[cb + 1], 0.f);
                float o2 = fmaxf(c[mt][nt][2] + sB1f[cb],     0.f);
                float o3 = fmaxf(c[mt][nt][3] + sB1f[cb + 1], 0.f);
                split2(o0, o1, phi[mt][nt][0], plo[mt][nt][0]);
                split2(o2, o3, phi[mt][nt][1], plo[mt][nt][1]);
            }
        }
        #pragma unroll
        for (int mt = 0; mt < 2; mt++)
            #pragma unroll
            for (int nt = 0; nt < 8; nt++)
                #pragma unroll
                for (int j = 0; j < 4; j++) c[mt][nt][j] = 0.f;

        // ---- layer-2 GEMM: A from registers, B frags from gmem ----
        #pragma unroll
        for (int ks = 0; ks < 4; ks++) {
            const int k0 = ks * 16;
            #pragma unroll
            for (int nt = 0; nt < 8; nt++) {
                const __half* pb = w2b + nt * 512 + k0;
                uint32_t b0 = __ldg((const uint32_t*)pb);
                uint32_t b1 = __ldg((const uint32_t*)(pb + 8));
                mma16816(c[0][nt], phi[0][2*ks][0], phi[0][2*ks][1],
                         phi[0][2*ks+1][0], phi[0][2*ks+1][1], b0, b1);
                mma16816(c[1][nt], phi[1][2*ks][0], phi[1][2*ks][1],
                         phi[1][2*ks+1][0], phi[1][2*ks+1][1], b0, b1);
                mma16816(c[0][nt], plo[0][2*ks][0], plo[0][2*ks][1],
                         plo[0][2*ks+1][0], plo[0][2*ks+1][1], b0, b1);
                mma16816(c[1][nt], plo[1][2*ks][0], plo[1][2*ks][1],
                         plo[1][2*ks+1][0], plo[1][2*ks+1][1], b0, b1);
            }
        }
    }

    // ---- epilogue: bias (+ relu for GIN block), store ----
    const float* bias = two_layer ? sB2f : sB1f;
    #pragma unroll
    for (int mt = 0; mt < 2; mt++) {
        int r0 = row0 + m0 + mt * 16 + g;
        int r1 = r0 + 8;
        #pragma unroll
        for (int nt = 0; nt < 8; nt++) {
            int cb = nt * 8 + tig * 2;
            float o0 = c[mt][nt][0] + bias[cb];
            float o1 = c[mt][nt][1] + bias[cb + 1];
            float o2 = c[mt][nt][2] + bias[cb];
            float o3 = c[mt][nt][3] + bias[cb + 1];
            if (two_layer) {
                o0 = fmaxf(o0, 0.f); o1 = fmaxf(o1, 0.f);
                o2 = fmaxf(o2, 0.f); o3 = fmaxf(o3, 0.f);
            }
            if (r0 < N_NODES) *(float2*)(out + (size_t)r0 * D + cb) = make_float2(o0, o1);
            if (r1 < N_NODES) *(float2*)(out + (size_t)r1 * D + cb) = make_float2(o2, o3);
        }
    }
}

// ===========================================================================
extern "C" void kernel_launch(void* const* d_in, const int* in_sizes, int n_in,
                              void* d_out, int out_size)
{
    const float* x  = (const float*)d_in[0];
    const void*  ei = d_in[1];

    static float*  agg = nullptr;
    static float*  buf = nullptr;
    static __half* wh  = nullptr;
    static bool init_done = false;
    if (!init_done) {
        cudaGetSymbolAddress((void**)&agg, g_agg);
        cudaGetSymbolAddress((void**)&buf, g_buf);
        cudaGetSymbolAddress((void**)&wh, g_wh);
        cudaFuncSetAttribute(mlp_tc_kernel, cudaFuncAttributeMaxDynamicSharedMemorySize, SM_TOT);
        init_done = true;
    }

    const int edge_grid = (E_EDGES + 255) / 256;
    const int node_grid = (N_NODES + 255) / 256;
    const int scan_grid = (N_NODES + 1023) / 1024;
    const int aggr_grid = (N_NODES + 15) / 16;
    const int mlp_grid  = (N_NODES + 127) / 128;

    // weight order in g_wh: w1_0, w2_0, w1_1, w2_1, w1_2, w2_2, wf
    WPtrs ws;
    ws.p[0] = (const float*)d_in[2];  ws.p[1] = (const float*)d_in[4];
    ws.p[2] = (const float*)d_in[6];  ws.p[3] = (const float*)d_in[8];
    ws.p[4] = (const float*)d_in[10]; ws.p[5] = (const float*)d_in[12];
    ws.p[6] = (const float*)d_in[14];

    zero_probe_wconv_kernel<<<node_grid, 256>>>((const int*)ei, ws);
    hist_kernel<<<edge_grid, 256>>>(ei);
    scan1_kernel<<<scan_grid, 1024>>>();
    scan23_kernel<<<scan_grid, 1024>>>();
    fill_kernel<<<edge_grid, 256>>>(ei);

    // Block 0
    aggregate_kernel<<<aggr_grid, 256>>>(x, agg);
    mlp_tc_kernel<<<mlp_grid, 128, SM_TOT>>>(agg, buf,
        wh + 0 * 4096, (const float*)d_in[3],
        wh + 1 * 4096, (const float*)d_in[5], 1);

    // Block 1
    aggregate_kernel<<<aggr_grid, 256>>>(buf, agg);
    mlp_tc_kernel<<<mlp_grid, 128, SM_TOT>>>(agg, buf,
        wh + 2 * 4096, (const float*)d_in[7],
        wh + 3 * 4096, (const float*)d_in[9], 1);

    // Block 2
    aggregate_kernel<<<aggr_grid, 256>>>(buf, agg);
    mlp_tc_kernel<<<mlp_grid, 128, SM_TOT>>>(agg, buf,
        wh + 4 * 4096, (const float*)d_in[11],
        wh + 5 * 4096, (const float*)d_in[13], 1);

    // Final linear
    mlp_tc_kernel<<<mlp_grid, 128, SM_TOT>>>(buf, (float*)d_out,
        wh + 6 * 4096, (const float*)d_in[15],
        nullptr, nullptr, 0);
}

// round 16
// speedup vs baseline: 1.2928x; 1.2928x over previous
#include <cuda_runtime.h>
#include <cuda_fp16.h>
#include <cstdint>

#define N_NODES 100000
#define E_EDGES 1600000
#define D 64

// Scratch (device globals: allocation-free per harness rules)
__device__ float  g_agg[(size_t)N_NODES * D];
__device__ float  g_buf[(size_t)N_NODES * D];
__device__ __half g_wh[7 * 4096];               // 7 pre-converted W^T fp16 planes
__device__ int    g_deg[N_NODES];
__device__ int    g_cur[N_NODES];
__device__ int    g_off[N_NODES];
__device__ int    g_srcs[E_EDGES];
__device__ int    g_part[128];
__device__ int    g_ei_is64;

struct WPtrs { const float* p[7]; };

// ===========================================================================
// zero + edge-index dtype probe + weight fp16 pre-conversion (one kernel)
// ===========================================================================
__global__ void zero_probe_wconv_kernel(const int* __restrict__ ei_i32, WPtrs ws) {
    __shared__ int nz;
    int t = threadIdx.x;
    int i = blockIdx.x * blockDim.x + t;
    if (i < N_NODES) { g_deg[i] = 0; g_cur[i] = 0; }
    if (blockIdx.x == 0) {
        if (t == 0) nz = 0;
        __syncthreads();
        if (t < 128 && ei_i32[2 * t + 1] != 0) atomicOr(&nz, 1);
        __syncthreads();
        if (t == 0) g_ei_is64 = (nz == 0) ? 1 : 0;
    } else if (blockIdx.x <= 7) {
        int m = blockIdx.x - 1;
        const float* w = ws.p[m];
        #pragma unroll 4
        for (int idx = t; idx < 4096; idx += 256) {
            int k = idx >> 6, n = idx & 63;      // w[k][n] -> wt[n][k]
            g_wh[m * 4096 + n * 64 + k] = __float2half_rn(__ldg(&w[idx]));
        }
    }
}

__device__ __forceinline__ int load_idx(const void* ei_raw, int pos) {
    if (g_ei_is64) return (int)__ldg(&((const long long*)ei_raw)[pos]);
    return __ldg(&((const int*)ei_raw)[pos]);
}

__global__ void hist_kernel(const void* __restrict__ ei_raw) {
    int e = blockIdx.x * blockDim.x + threadIdx.x;
    if (e >= E_EDGES) return;
    atomicAdd(&g_deg[load_idx(ei_raw, E_EDGES + e)], 1);
}

__global__ void __launch_bounds__(1024) scan1_kernel() {
    __shared__ int wsum[32];
    int i = blockIdx.x * 1024 + threadIdx.x;
    int v = (i < N_NODES) ? g_deg[i] : 0;
    int lane = threadIdx.x & 31, wid = threadIdx.x >> 5;
    int incl = v;
    #pragma unroll
    for (int d = 1; d < 32; d <<= 1) {
        int n = __shfl_up_sync(~0u, incl, d);
        if (lane >= d) incl += n;
    }
    if (lane == 31) wsum[wid] = incl;
    __syncthreads();
    if (wid == 0) {
        int s = wsum[lane];
        #pragma unroll
        for (int d = 1; d < 32; d <<= 1) {
            int n = __shfl_up_sync(~0u, s, d);
            if (lane >= d) s += n;
        }
        wsum[lane] = s;
    }
    __syncthreads();
    int woff = (wid > 0) ? wsum[wid - 1] : 0;
    if (i < N_NODES) g_off[i] = woff + incl - v;
    if (threadIdx.x == 1023) g_part[blockIdx.x] = woff + incl;
}

// Fused scan2+scan3
__global__ void __launch_bounds__(1024) scan23_kernel() {
    __shared__ int ssum[32];
    int t = threadIdx.x;
    int lane = t & 31, wid = t >> 5;
    int v = (t < blockIdx.x) ? g_part[t] : 0;
    #pragma unroll
    for (int d = 16; d >= 1; d >>= 1) v += __shfl_down_sync(~0u, v, d);
    if (lane == 0) ssum[wid] = v;
    __syncthreads();
    if (wid == 0) {
        int s = ssum[lane];
        #pragma unroll
        for (int d = 16; d >= 1; d >>= 1) s += __shfl_down_sync(~0u, s, d);
        if (lane == 0) ssum[0] = s;
    }
    __syncthreads();
    int add = ssum[0];
    int i = blockIdx.x * 1024 + t;
    if (i < N_NODES) g_off[i] += add;
}

__global__ void fill_kernel(const void* __restrict__ ei_raw) {
    int e = blockIdx.x * blockDim.x + threadIdx.x;
    if (e >= E_EDGES) return;
    int src = load_idx(ei_raw, e);
    int dst = load_idx(ei_raw, E_EDGES + e);
    g_srcs[g_off[dst] + atomicAdd(&g_cur[dst], 1)] = src;
}

// ===========================================================================
// agg[i] = x[i] + sum_{j in bucket(i)} x[srcs[j]]   (no atomics)
// ===========================================================================
__global__ void __launch_bounds__(256) aggregate_kernel(
    const float* __restrict__ x, float* __restrict__ agg)
{
    int node = blockIdx.x * 16 + (threadIdx.x >> 4);
    int c = threadIdx.x & 15;
    if (node >= N_NODES) return;

    int beg = __ldg(&g_off[node]);
    int cnt = __ldg(&g_deg[node]);
    float4 v = __ldg((const float4*)(x + (size_t)node * D) + c);

    int j = 0;
    for (; j + 2 <= cnt; j += 2) {
        int s0 = __ldg(&g_srcs[beg + j]);
        int s1 = __ldg(&g_srcs[beg + j + 1]);
        float4 u0 = __ldg((const float4*)(x + (size_t)s0 * D) + c);
        float4 u1 = __ldg((const float4*)(x + (size_t)s1 * D) + c);
        v.x += u0.x + u1.x; v.y += u0.y + u1.y;
        v.z += u0.z + u1.z; v.w += u0.w + u1.w;
    }
    if (j < cnt) {
        int s0 = __ldg(&g_srcs[beg + j]);
        float4 u0 = __ldg((const float4*)(x + (size_t)s0 * D) + c);
        v.x += u0.x; v.y += u0.y; v.z += u0.z; v.w += u0.w;
    }
    *((float4*)(agg + (size_t)node * D) + c) = v;
}

// ===========================================================================
// Tensor-core MLP via mma.sync.m16n8k16 FP16, 2-product split (R12 numerics).
// R16: weights in smem (R14 — the fast config). A fragments loaded DIRECTLY
// from gmem into registers: each float2 yields both hi+lo planes via one
// packed split2 -> 32 LDG.64/thread replaces 16 LDG.128 + 32 STS + 32 LDS,
// A smem eliminated (smem 19KB), A-staging barrier pressure gone.
// CTA = 128 threads / 128 rows; warp w: rows 32w..32w+31, all 64 cols.
// ===========================================================================
#define SR 72

#define SM_BIAS1 0
#define SM_BIAS2 256
#define SM_B1    512
#define SM_B2    (SM_B1 + 64 * SR * 2)
#define SM_TOT   (SM_B2 + 64 * SR * 2)    // 18944 bytes

// packed split: (x0,x1) -> hi pair + lo pair (exact fp16 decomposition, rn)
__device__ __forceinline__ void split2(float x0, float x1,
                                       uint32_t& ph, uint32_t& pl) {
    __half2 h = __floats2half2_rn(x0, x1);
    float2 hf = __half22float2(h);
    __half2 l = __floats2half2_rn(x0 - hf.x, x1 - hf.y);
    ph = *(uint32_t*)&h;
    pl = *(uint32_t*)&l;
}

// NON-volatile: pure computation, lets the compiler schedule.
__device__ __forceinline__ void mma16816(float c[4], uint32_t a0, uint32_t a1,
                                         uint32_t a2, uint32_t a3,
                                         uint32_t b0, uint32_t b1) {
    asm("mma.sync.aligned.m16n8k16.row.col.f32.f16.f16.f32 "
        "{%0,%1,%2,%3}, {%4,%5,%6,%7}, {%8,%9}, {%0,%1,%2,%3};"
        : "+f"(c[0]), "+f"(c[1]), "+f"(c[2]), "+f"(c[3])
        : "r"(a0), "r"(a1), "r"(a2), "r"(a3), "r"(b0), "r"(b1));
}

// stage pre-converted W^T plane: pure uint4 copy, all 128 threads
__device__ __forceinline__ void stage_wh(const __half* __restrict__ wt,
                                         __half* b, int t)
{
    #pragma unroll
    for (int j = 0; j < 4; j++) {
        int i = t + j * 128;               // 512 uint4 total
        int n = i >> 3, k8 = i & 7;
        *(uint4*)(b + n * SR + k8 * 8) = __ldg((const uint4*)wt + i);
    }
}

__global__ void __launch_bounds__(128) mlp_tc_kernel(
    const float* __restrict__ in, float* __restrict__ out,
    const __half* __restrict__ w1t, const float* __restrict__ b1,
    const __half* __restrict__ w2t, const float* __restrict__ b2,
    int two_layer)
{
    extern __shared__ char smem[];
    float* sB1f = (float*)(smem + SM_BIAS1);
    float* sB2f = (float*)(smem + SM_BIAS2);
    __half* sB1 = (__half*)(smem + SM_B1);
    __half* sB2 = (__half*)(smem + SM_B2);

    const int t = threadIdx.x;
    const int warp = t >> 5, lane = t & 31;
    const int g = lane >> 2, tig = lane & 3;
    const int m0 = warp * 32;
    const int row0 = blockIdx.x * 128;

    // ---- stage B planes (pure uint4 copies) + biases ----
    stage_wh(w1t, sB1, t);
    if (two_layer) stage_wh(w2t, sB2, t);
    if (t < 16) ((float4*)sB1f)[t] = __ldg((const float4*)b1 + t);
    else if (t < 32 && two_layer) ((float4*)sB2f)[t - 16] = __ldg((const float4*)b2 + (t - 16));
    __syncthreads();   // the ONLY barrier

    // thread's two global rows (per mt): r0g = row0+m0+mt*16+g, r1g = r0g+8
    const int rA = row0 + m0 + g;
    const int rB = rA + 8;
    const int rC = rA + 16;
    const int rD = rA + 24;
    const bool vA = rA < N_NODES, vB = rB < N_NODES;
    const bool vC = rC < N_NODES, vD = rD < N_NODES;
    const float* pA = in + (size_t)rA * D + tig * 2;
    const float* pB = in + (size_t)rB * D + tig * 2;
    const float* pC = in + (size_t)rC * D + tig * 2;
    const float* pD = in + (size_t)rD * D + tig * 2;

    float c[2][8][4];
    #pragma unroll
    for (int mt = 0; mt < 2; mt++)
        #pragma unroll
        for (int nt = 0; nt < 8; nt++)
            #pragma unroll
            for (int j = 0; j < 4; j++) c[mt][nt][j] = 0.f;

    const float2 z2 = make_float2(0.f, 0.f);

    // ---- layer-1 GEMM: A direct gmem->regs (one split2 per float2), B smem ----
    #pragma unroll
    for (int ks = 0; ks < 4; ks++) {
        const int k0 = ks * 16;
        uint32_t ah[2][4], al[2][4];
        {
            float2 f0 = vA ? __ldg((const float2*)(pA + k0))     : z2;
            float2 f1 = vB ? __ldg((const float2*)(pB + k0))     : z2;
            float2 f2 = vA ? __ldg((const float2*)(pA + k0 + 8)) : z2;
            float2 f3 = vB ? __ldg((const float2*)(pB + k0 + 8)) : z2;
            split2(f0.x, f0.y, ah[0][0], al[0][0]);
            split2(f1.x, f1.y, ah[0][1], al[0][1]);
            split2(f2.x, f2.y, ah[0][2], al[0][2]);
            split2(f3.x, f3.y, ah[0][3], al[0][3]);
        }
        {
            float2 f0 = vC ? __ldg((const float2*)(pC + k0))     : z2;
            float2 f1 = vD ? __ldg((const float2*)(pD + k0))     : z2;
            float2 f2 = vC ? __ldg((const float2*)(pC + k0 + 8)) : z2;
            float2 f3 = vD ? __ldg((const float2*)(pD + k0 + 8)) : z2;
            split2(f0.x, f0.y, ah[1][0], al[1][0]);
            split2(f1.x, f1.y, ah[1][1], al[1][1]);
            split2(f2.x, f2.y, ah[1][2], al[1][2]);
            split2(f3.x, f3.y, ah[1][3], al[1][3]);
        }
        #pragma unroll
        for (int nt = 0; nt < 8; nt++) {
            const __half* pb = sB1 + (nt * 8 + g) * SR + k0 + tig * 2;
            uint32_t b0 = *(const uint32_t*)pb, b1 = *(const uint32_t*)(pb + 8);
            mma16816(c[0][nt], ah[0][0], ah[0][1], ah[0][2], ah[0][3], b0, b1);
            mma16816(c[1][nt], ah[1][0], ah[1][1], ah[1][2], ah[1][3], b0, b1);
            mma16816(c[0][nt], al[0][0], al[0][1], al[0][2], al[0][3], b0, b1);
            mma16816(c[1][nt], al[1][0], al[1][1], al[1][2], al[1][3], b0, b1);
        }
    }

    if (two_layer) {
        // ---- h1 = relu(c + b1): packed split IN REGISTERS ----
        uint32_t phi[2][8][2], plo[2][8][2];
        #pragma unroll
        for (int mt = 0; mt < 2; mt++) {
            #pragma unroll
            for (int nt = 0; nt < 8; nt++) {
                int cb = nt * 8 + tig * 2;
                float o0 = fmaxf(c[mt][nt][0] + sB1f[cb],     0.f);
                float o1 = fmaxf(c[mt][nt][1] + sB1f[cb + 1], 0.f);
                float o2 = fmaxf(c[mt][nt][2] + sB1f[cb],     0.f);
                float o3 = fmaxf(c[mt][nt][3] + sB1f[cb + 1], 0.f);
                split2(o0, o1, phi[mt][nt][0], plo[mt][nt][0]);
                split2(o2, o3, phi[mt][nt][1], plo[mt][nt][1]);
            }
        }
        #pragma unroll
        for (int mt = 0; mt < 2; mt++)
            #pragma unroll
            for (int nt = 0; nt < 8; nt++)
                #pragma unroll
                for (int j = 0; j < 4; j++) c[mt][nt][j] = 0.f;

        // ---- layer-2 GEMM: A from registers, B from smem ----
        #pragma unroll
        for (int ks = 0; ks < 4; ks++) {
            const int k0 = ks * 16;
            #pragma unroll
            for (int nt = 0; nt < 8; nt++) {
                const __half* pb = sB2 + (nt * 8 + g) * SR + k0 + tig * 2;
                uint32_t b0 = *(const uint32_t*)pb, b1 = *(const uint32_t*)(pb + 8);
                mma16816(c[0][nt], phi[0][2*ks][0], phi[0][2*ks][1],
                         phi[0][2*ks+1][0], phi[0][2*ks+1][1], b0, b1);
                mma16816(c[1][nt], phi[1][2*ks][0], phi[1][2*ks][1],
                         phi[1][2*ks+1][0], phi[1][2*ks+1][1], b0, b1);
                mma16816(c[0][nt], plo[0][2*ks][0], plo[0][2*ks][1],
                         plo[0][2*ks+1][0], plo[0][2*ks+1][1], b0, b1);
                mma16816(c[1][nt], plo[1][2*ks][0], plo[1][2*ks][1],
                         plo[1][2*ks+1][0], plo[1][2*ks+1][1], b0, b1);
            }
        }
    }

    // ---- epilogue: bias (+ relu for GIN block), store ----
    const float* bias = two_layer ? sB2f : sB1f;
    #pragma unroll
    for (int mt = 0; mt < 2; mt++) {
        int r0 = row0 + m0 + mt * 16 + g;
        int r1 = r0 + 8;
        #pragma unroll
        for (int nt = 0; nt < 8; nt++) {
            int cb = nt * 8 + tig * 2;
            float o0 = c[mt][nt][0] + bias[cb];
            float o1 = c[mt][nt][1] + bias[cb + 1];
            float o2 = c[mt][nt][2] + bias[cb];
            float o3 = c[mt][nt][3] + bias[cb + 1];
            if (two_layer) {
                o0 = fmaxf(o0, 0.f); o1 = fmaxf(o1, 0.f);
                o2 = fmaxf(o2, 0.f); o3 = fmaxf(o3, 0.f);
            }
            if (r0 < N_NODES) *(float2*)(out + (size_t)r0 * D + cb) = make_float2(o0, o1);
            if (r1 < N_NODES) *(float2*)(out + (size_t)r1 * D + cb) = make_float2(o2, o3);
        }
    }
}

// ===========================================================================
extern "C" void kernel_launch(void* const* d_in, const int* in_sizes, int n_in,
                              void* d_out, int out_size)
{
    const float* x  = (const float*)d_in[0];
    const void*  ei = d_in[1];

    static float*  agg = nullptr;
    static float*  buf = nullptr;
    static __half* wh  = nullptr;
    static bool init_done = false;
    if (!init_done) {
        cudaGetSymbolAddress((void**)&agg, g_agg);
        cudaGetSymbolAddress((void**)&buf, g_buf);
        cudaGetSymbolAddress((void**)&wh, g_wh);
        cudaFuncSetAttribute(mlp_tc_kernel, cudaFuncAttributeMaxDynamicSharedMemorySize, SM_TOT);
        init_done = true;
    }

    const int edge_grid = (E_EDGES + 255) / 256;
    const int node_grid = (N_NODES + 255) / 256;
    const int scan_grid = (N_NODES + 1023) / 1024;
    const int aggr_grid = (N_NODES + 15) / 16;
    const int mlp_grid  = (N_NODES + 127) / 128;

    // weight order in g_wh: w1_0, w2_0, w1_1, w2_1, w1_2, w2_2, wf
    WPtrs ws;
    ws.p[0] = (const float*)d_in[2];  ws.p[1] = (const float*)d_in[4];
    ws.p[2] = (const float*)d_in[6];  ws.p[3] = (const float*)d_in[8];
    ws.p[4] = (const float*)d_in[10]; ws.p[5] = (const float*)d_in[12];
    ws.p[6] = (const float*)d_in[14];

    zero_probe_wconv_kernel<<<node_grid, 256>>>((const int*)ei, ws);
    hist_kernel<<<edge_grid, 256>>>(ei);
    scan1_kernel<<<scan_grid, 1024>>>();
    scan23_kernel<<<scan_grid, 1024>>>();
    fill_kernel<<<edge_grid, 256>>>(ei);

    // Block 0
    aggregate_kernel<<<aggr_grid, 256>>>(x, agg);
    mlp_tc_kernel<<<mlp_grid, 128, SM_TOT>>>(agg, buf,
        wh + 0 * 4096, (const float*)d_in[3],
        wh + 1 * 4096, (const float*)d_in[5], 1);

    // Block 1
    aggregate_kernel<<<aggr_grid, 256>>>(buf, agg);
    mlp_tc_kernel<<<mlp_grid, 128, SM_TOT>>>(agg, buf,
        wh + 2 * 4096, (const float*)d_in[7],
        wh + 3 * 4096, (const float*)d_in[9], 1);

    // Block 2
    aggregate_kernel<<<aggr_grid, 256>>>(buf, agg);
    mlp_tc_kernel<<<mlp_grid, 128, SM_TOT>>>(agg, buf,
        wh + 4 * 4096, (const float*)d_in[11],
        wh + 5 * 4096, (const float*)d_in[13], 1);

    // Final linear
    mlp_tc_kernel<<<mlp_grid, 128, SM_TOT>>>(buf, (float*)d_out,
        wh + 6 * 4096, (const float*)d_in[15],
        nullptr, nullptr, 0);
}

// round 17
// speedup vs baseline: 1.3745x; 1.0632x over previous
#include <cuda_runtime.h>
#include <cuda_fp16.h>
#include <cstdint>

#define N_NODES 100000
#define E_EDGES 1600000
#define D 64

// Scratch (device globals: allocation-free per harness rules)
__device__ float  g_agg[(size_t)N_NODES * D];
__device__ float  g_buf[(size_t)N_NODES * D];
__device__ __half g_wh[7 * 4096];               // 7 pre-converted W^T fp16 planes
__device__ int    g_deg[N_NODES];
__device__ int    g_cur[N_NODES];
__device__ int    g_off[N_NODES];
__device__ int    g_srcs[E_EDGES];
__device__ int    g_part[128];
__device__ int    g_ei_is64;

struct WPtrs { const float* p[7]; };

// ===========================================================================
// zero + edge-index dtype probe + weight fp16 pre-conversion (one kernel)
// ===========================================================================
__global__ void zero_probe_wconv_kernel(const int* __restrict__ ei_i32, WPtrs ws) {
    __shared__ int nz;
    int t = threadIdx.x;
    int i = blockIdx.x * blockDim.x + t;
    if (i < N_NODES) { g_deg[i] = 0; g_cur[i] = 0; }
    if (blockIdx.x == 0) {
        if (t == 0) nz = 0;
        __syncthreads();
        if (t < 128 && ei_i32[2 * t + 1] != 0) atomicOr(&nz, 1);
        __syncthreads();
        if (t == 0) g_ei_is64 = (nz == 0) ? 1 : 0;
    } else if (blockIdx.x <= 7) {
        int m = blockIdx.x - 1;
        const float* w = ws.p[m];
        #pragma unroll 4
        for (int idx = t; idx < 4096; idx += 256) {
            int k = idx >> 6, n = idx & 63;      // w[k][n] -> wt[n][k]
            g_wh[m * 4096 + n * 64 + k] = __float2half_rn(__ldg(&w[idx]));
        }
    }
}

__device__ __forceinline__ int load_idx(const void* ei_raw, int pos) {
    if (g_ei_is64) return (int)__ldg(&((const long long*)ei_raw)[pos]);
    return __ldg(&((const int*)ei_raw)[pos]);
}

__global__ void hist_kernel(const void* __restrict__ ei_raw) {
    int e = blockIdx.x * blockDim.x + threadIdx.x;
    if (e >= E_EDGES) return;
    atomicAdd(&g_deg[load_idx(ei_raw, E_EDGES + e)], 1);
}

__global__ void __launch_bounds__(1024) scan1_kernel() {
    __shared__ int wsum[32];
    int i = blockIdx.x * 1024 + threadIdx.x;
    int v = (i < N_NODES) ? g_deg[i] : 0;
    int lane = threadIdx.x & 31, wid = threadIdx.x >> 5;
    int incl = v;
    #pragma unroll
    for (int d = 1; d < 32; d <<= 1) {
        int n = __shfl_up_sync(~0u, incl, d);
        if (lane >= d) incl += n;
    }
    if (lane == 31) wsum[wid] = incl;
    __syncthreads();
    if (wid == 0) {
        int s = wsum[lane];
        #pragma unroll
        for (int d = 1; d < 32; d <<= 1) {
            int n = __shfl_up_sync(~0u, s, d);
            if (lane >= d) s += n;
        }
        wsum[lane] = s;
    }
    __syncthreads();
    int woff = (wid > 0) ? wsum[wid - 1] : 0;
    if (i < N_NODES) g_off[i] = woff + incl - v;
    if (threadIdx.x == 1023) g_part[blockIdx.x] = woff + incl;
}

// Fused scan2+scan3
__global__ void __launch_bounds__(1024) scan23_kernel() {
    __shared__ int ssum[32];
    int t = threadIdx.x;
    int lane = t & 31, wid = t >> 5;
    int v = (t < blockIdx.x) ? g_part[t] : 0;
    #pragma unroll
    for (int d = 16; d >= 1; d >>= 1) v += __shfl_down_sync(~0u, v, d);
    if (lane == 0) ssum[wid] = v;
    __syncthreads();
    if (wid == 0) {
        int s = ssum[lane];
        #pragma unroll
        for (int d = 16; d >= 1; d >>= 1) s += __shfl_down_sync(~0u, s, d);
        if (lane == 0) ssum[0] = s;
    }
    __syncthreads();
    int add = ssum[0];
    int i = blockIdx.x * 1024 + t;
    if (i < N_NODES) g_off[i] += add;
}

__global__ void fill_kernel(const void* __restrict__ ei_raw) {
    int e = blockIdx.x * blockDim.x + threadIdx.x;
    if (e >= E_EDGES) return;
    int src = load_idx(ei_raw, e);
    int dst = load_idx(ei_raw, E_EDGES + e);
    g_srcs[g_off[dst] + atomicAdd(&g_cur[dst], 1)] = src;
}

// ===========================================================================
// agg[i] = x[i] + sum_{j in bucket(i)} x[srcs[j]]   (no atomics)
// ===========================================================================
__global__ void __launch_bounds__(256) aggregate_kernel(
    const float* __restrict__ x, float* __restrict__ agg)
{
    int node = blockIdx.x * 16 + (threadIdx.x >> 4);
    int c = threadIdx.x & 15;
    if (node >= N_NODES) return;

    int beg = __ldg(&g_off[node]);
    int cnt = __ldg(&g_deg[node]);
    float4 v = __ldg((const float4*)(x + (size_t)node * D) + c);

    int j = 0;
    for (; j + 2 <= cnt; j += 2) {
        int s0 = __ldg(&g_srcs[beg + j]);
        int s1 = __ldg(&g_srcs[beg + j + 1]);
        float4 u0 = __ldg((const float4*)(x + (size_t)s0 * D) + c);
        float4 u1 = __ldg((const float4*)(x + (size_t)s1 * D) + c);
        v.x += u0.x + u1.x; v.y += u0.y + u1.y;
        v.z += u0.z + u1.z; v.w += u0.w + u1.w;
    }
    if (j < cnt) {
        int s0 = __ldg(&g_srcs[beg + j]);
        float4 u0 = __ldg((const float4*)(x + (size_t)s0 * D) + c);
        v.x += u0.x; v.y += u0.y; v.z += u0.z; v.w += u0.w;
    }
    *((float4*)(agg + (size_t)node * D) + c) = v;
}

// ===========================================================================
// Tensor-core MLP via mma.sync.m16n8k16 FP16, 2-product split (R12 numerics).
// R17 = R14 base (A staged in smem, B planes staged from pre-converted g_wh)
//  + packed split2 (cvt.rn.f16x2.f32)
//  + n_layers=3 mode: block-2 GIN MLP fuses the FINAL LINEAR (w3=wf) and
//    writes d_out directly -> one whole MLP launch (and its 51MB round trip)
//    deleted. 2-layer launches pass smem to SM_B3 only (4 CTAs/SM unchanged).
// CTA = 128 threads / 128 rows; warp w: rows 32w..32w+31, all 64 cols.
// ===========================================================================
#define SR 72

#define SM_BIAS1 0
#define SM_BIAS2 256
#define SM_BIAS3 512
#define SM_AHI   768
#define SM_ALO   (SM_AHI + 128 * SR * 2)
#define SM_B1    (SM_ALO + 128 * SR * 2)
#define SM_B2    (SM_B1  + 64 * SR * 2)
#define SM_B3    (SM_B2  + 64 * SR * 2)
#define SM_TOT2  SM_B3                     // 2-layer launches: 56064 B
#define SM_TOT3  (SM_B3 + 64 * SR * 2)     // 3-layer launch:   65280 B

// packed split: (x0,x1) -> hi pair + lo pair (exact fp16 decomposition, rn)
__device__ __forceinline__ void split2(float x0, float x1,
                                       uint32_t& ph, uint32_t& pl) {
    __half2 h = __floats2half2_rn(x0, x1);
    float2 hf = __half22float2(h);
    __half2 l = __floats2half2_rn(x0 - hf.x, x1 - hf.y);
    ph = *(uint32_t*)&h;
    pl = *(uint32_t*)&l;
}

// NON-volatile: pure computation, lets the compiler schedule.
__device__ __forceinline__ void mma16816(float c[4], uint32_t a0, uint32_t a1,
                                         uint32_t a2, uint32_t a3,
                                         uint32_t b0, uint32_t b1) {
    asm("mma.sync.aligned.m16n8k16.row.col.f32.f16.f16.f32 "
        "{%0,%1,%2,%3}, {%4,%5,%6,%7}, {%8,%9}, {%0,%1,%2,%3};"
        : "+f"(c[0]), "+f"(c[1]), "+f"(c[2]), "+f"(c[3])
        : "r"(a0), "r"(a1), "r"(a2), "r"(a3), "r"(b0), "r"(b1));
}

// stage pre-converted W^T plane: pure uint4 copy, all 128 threads
__device__ __forceinline__ void stage_wh(const __half* __restrict__ wt,
                                         __half* b, int t)
{
    #pragma unroll
    for (int j = 0; j < 4; j++) {
        int i = t + j * 128;               // 512 uint4 total
        int n = i >> 3, k8 = i & 7;
        *(uint4*)(b + n * SR + k8 * 8) = __ldg((const uint4*)wt + i);
    }
}

// relu(c+bias) -> packed hi/lo A-fragments in registers, then zero c
__device__ __forceinline__ void relu_split_regs(
    float c[2][8][4], const float* bias, int tig,
    uint32_t phi[2][8][2], uint32_t plo[2][8][2])
{
    #pragma unroll
    for (int mt = 0; mt < 2; mt++) {
        #pragma unroll
        for (int nt = 0; nt < 8; nt++) {
            int cb = nt * 8 + tig * 2;
            float o0 = fmaxf(c[mt][nt][0] + bias[cb],     0.f);
            float o1 = fmaxf(c[mt][nt][1] + bias[cb + 1], 0.f);
            float o2 = fmaxf(c[mt][nt][2] + bias[cb],     0.f);
            float o3 = fmaxf(c[mt][nt][3] + bias[cb + 1], 0.f);
            split2(o0, o1, phi[mt][nt][0], plo[mt][nt][0]);
            split2(o2, o3, phi[mt][nt][1], plo[mt][nt][1]);
        }
    }
    #pragma unroll
    for (int mt = 0; mt < 2; mt++)
        #pragma unroll
        for (int nt = 0; nt < 8; nt++)
            #pragma unroll
            for (int j = 0; j < 4; j++) c[mt][nt][j] = 0.f;
}

// GEMM with A-fragments in registers, B plane in smem
__device__ __forceinline__ void gemm_regA(
    const uint32_t phi[2][8][2], const uint32_t plo[2][8][2],
    const __half* __restrict__ B, float c[2][8][4], int g, int tig)
{
    #pragma unroll
    for (int ks = 0; ks < 4; ks++) {
        const int k0 = ks * 16;
        #pragma unroll
        for (int nt = 0; nt < 8; nt++) {
            const __half* pb = B + (nt * 8 + g) * SR + k0 + tig * 2;
            uint32_t b0 = *(const uint32_t*)pb, b1 = *(const uint32_t*)(pb + 8);
            mma16816(c[0][nt], phi[0][2*ks][0], phi[0][2*ks][1],
                     phi[0][2*ks+1][0], phi[0][2*ks+1][1], b0, b1);
            mma16816(c[1][nt], phi[1][2*ks][0], phi[1][2*ks][1],
                     phi[1][2*ks+1][0], phi[1][2*ks+1][1], b0, b1);
            mma16816(c[0][nt], plo[0][2*ks][0], plo[0][2*ks][1],
                     plo[0][2*ks+1][0], plo[0][2*ks+1][1], b0, b1);
            mma16816(c[1][nt], plo[1][2*ks][0], plo[1][2*ks][1],
                     plo[1][2*ks+1][0], plo[1][2*ks+1][1], b0, b1);
        }
    }
}

__global__ void __launch_bounds__(128) mlp_tc_kernel(
    const float* __restrict__ in, float* __restrict__ out,
    const __half* __restrict__ w1t, const float* __restrict__ b1,
    const __half* __restrict__ w2t, const float* __restrict__ b2,
    const __half* __restrict__ w3t, const float* __restrict__ b3,
    int n_layers)   // 1: final linear only; 2: GIN block; 3: GIN block + final
{
    extern __shared__ char smem[];
    float* sB1f = (float*)(smem + SM_BIAS1);
    float* sB2f = (float*)(smem + SM_BIAS2);
    float* sB3f = (float*)(smem + SM_BIAS3);
    __half* sAhi = (__half*)(smem + SM_AHI);
    __half* sAlo = (__half*)(smem + SM_ALO);
    __half* sB1  = (__half*)(smem + SM_B1);
    __half* sB2  = (__half*)(smem + SM_B2);
    __half* sB3  = (__half*)(smem + SM_B3);

    const int t = threadIdx.x;
    const int warp = t >> 5, lane = t & 31;
    const int g = lane >> 2, tig = lane & 3;
    const int m0 = warp * 32;
    const int row0 = blockIdx.x * 128;

    // ---- stage A (hi/lo fp16 split, packed cvts): coalesced float4 reads ----
    #pragma unroll
    for (int i = 0; i < 16; i++) {
        int idx4 = t + i * 128;
        int r = idx4 >> 4, c4 = idx4 & 15;
        int gr = row0 + r;
        float4 v = make_float4(0.f, 0.f, 0.f, 0.f);
        if (gr < N_NODES) v = __ldg((const float4*)(in + (size_t)gr * D) + c4);
        uint32_t* ph = (uint32_t*)(sAhi + r * SR + c4 * 4);
        uint32_t* pl = (uint32_t*)(sAlo + r * SR + c4 * 4);
        split2(v.x, v.y, ph[0], pl[0]);
        split2(v.z, v.w, ph[1], pl[1]);
    }
    // ---- stage W planes (pure copies) + biases ----
    stage_wh(w1t, sB1, t);
    if (n_layers >= 2) stage_wh(w2t, sB2, t);
    if (n_layers >= 3) stage_wh(w3t, sB3, t);
    if (t < 16) ((float4*)sB1f)[t] = __ldg((const float4*)b1 + t);
    else if (t < 32 && n_layers >= 2) ((float4*)sB2f)[t - 16] = __ldg((const float4*)b2 + (t - 16));
    else if (t >= 32 && t < 48 && n_layers >= 3) ((float4*)sB3f)[t - 32] = __ldg((const float4*)b3 + (t - 32));
    __syncthreads();   // the ONLY barrier

    float c[2][8][4];
    #pragma unroll
    for (int mt = 0; mt < 2; mt++)
        #pragma unroll
        for (int nt = 0; nt < 8; nt++)
            #pragma unroll
            for (int j = 0; j < 4; j++) c[mt][nt][j] = 0.f;

    // ---- layer-1 GEMM: A from smem, B from smem ----
    #pragma unroll
    for (int ks = 0; ks < 4; ks++) {
        const int k0 = ks * 16;
        uint32_t ah[2][4], al[2][4];
        #pragma unroll
        for (int mt = 0; mt < 2; mt++) {
            const __half* p0 = sAhi + (m0 + mt * 16 + g) * SR + k0 + tig * 2;
            const __half* q0 = sAlo + (m0 + mt * 16 + g) * SR + k0 + tig * 2;
            ah[mt][0] = *(const uint32_t*)p0;
            ah[mt][1] = *(const uint32_t*)(p0 + 8 * SR);
            ah[mt][2] = *(const uint32_t*)(p0 + 8);
            ah[mt][3] = *(const uint32_t*)(p0 + 8 * SR + 8);
            al[mt][0] = *(const uint32_t*)q0;
            al[mt][1] = *(const uint32_t*)(q0 + 8 * SR);
            al[mt][2] = *(const uint32_t*)(q0 + 8);
            al[mt][3] = *(const uint32_t*)(q0 + 8 * SR + 8);
        }
        #pragma unroll
        for (int nt = 0; nt < 8; nt++) {
            const __half* pb = sB1 + (nt * 8 + g) * SR + k0 + tig * 2;
            uint32_t b0 = *(const uint32_t*)pb, b1 = *(const uint32_t*)(pb + 8);
            mma16816(c[0][nt], ah[0][0], ah[0][1], ah[0][2], ah[0][3], b0, b1);
            mma16816(c[1][nt], ah[1][0], ah[1][1], ah[1][2], ah[1][3], b0, b1);
            mma16816(c[0][nt], al[0][0], al[0][1], al[0][2], al[0][3], b0, b1);
            mma16816(c[1][nt], al[1][0], al[1][1], al[1][2], al[1][3], b0, b1);
        }
    }

    if (n_layers >= 2) {
        uint32_t phi[2][8][2], plo[2][8][2];
        relu_split_regs(c, sB1f, tig, phi, plo);     // h1 = relu(c+b1)
        gemm_regA(phi, plo, sB2, c, g, tig);         // layer 2
        if (n_layers >= 3) {
            relu_split_regs(c, sB2f, tig, phi, plo); // h2 = relu(c+b2)
            gemm_regA(phi, plo, sB3, c, g, tig);     // layer 3 (final linear)
        }
    }

    // ---- epilogue: bias (+ relu only for 2-layer GIN block), store ----
    const float* bias = (n_layers == 1) ? sB1f : (n_layers == 2) ? sB2f : sB3f;
    const bool do_relu = (n_layers == 2);
    #pragma unroll
    for (int mt = 0; mt < 2; mt++) {
        int r0 = row0 + m0 + mt * 16 + g;
        int r1 = r0 + 8;
        #pragma unroll
        for (int nt = 0; nt < 8; nt++) {
            int cb = nt * 8 + tig * 2;
            float o0 = c[mt][nt][0] + bias[cb];
            float o1 = c[mt][nt][1] + bias[cb + 1];
            float o2 = c[mt][nt][2] + bias[cb];
            float o3 = c[mt][nt][3] + bias[cb + 1];
            if (do_relu) {
                o0 = fmaxf(o0, 0.f); o1 = fmaxf(o1, 0.f);
                o2 = fmaxf(o2, 0.f); o3 = fmaxf(o3, 0.f);
            }
            if (r0 < N_NODES) *(float2*)(out + (size_t)r0 * D + cb) = make_float2(o0, o1);
            if (r1 < N_NODES) *(float2*)(out + (size_t)r1 * D + cb) = make_float2(o2, o3);
        }
    }
}

// ===========================================================================
extern "C" void kernel_launch(void* const* d_in, const int* in_sizes, int n_in,
                              void* d_out, int out_size)
{
    const float* x  = (const float*)d_in[0];
    const void*  ei = d_in[1];

    static float*  agg = nullptr;
    static float*  buf = nullptr;
    static __half* wh  = nullptr;
    static bool init_done = false;
    if (!init_done) {
        cudaGetSymbolAddress((void**)&agg, g_agg);
        cudaGetSymbolAddress((void**)&buf, g_buf);
        cudaGetSymbolAddress((void**)&wh, g_wh);
        cudaFuncSetAttribute(mlp_tc_kernel, cudaFuncAttributeMaxDynamicSharedMemorySize, SM_TOT3);
        init_done = true;
    }

    const int edge_grid = (E_EDGES + 255) / 256;
    const int node_grid = (N_NODES + 255) / 256;
    const int scan_grid = (N_NODES + 1023) / 1024;
    const int aggr_grid = (N_NODES + 15) / 16;
    const int mlp_grid  = (N_NODES + 127) / 128;

    // weight order in g_wh: w1_0, w2_0, w1_1, w2_1, w1_2, w2_2, wf
    WPtrs ws;
    ws.p[0] = (const float*)d_in[2];  ws.p[1] = (const float*)d_in[4];
    ws.p[2] = (const float*)d_in[6];  ws.p[3] = (const float*)d_in[8];
    ws.p[4] = (const float*)d_in[10]; ws.p[5] = (const float*)d_in[12];
    ws.p[6] = (const float*)d_in[14];

    zero_probe_wconv_kernel<<<node_grid, 256>>>((const int*)ei, ws);
    hist_kernel<<<edge_grid, 256>>>(ei);
    scan1_kernel<<<scan_grid, 1024>>>();
    scan23_kernel<<<scan_grid, 1024>>>();
    fill_kernel<<<edge_grid, 256>>>(ei);

    // Block 0 (2 layers)
    aggregate_kernel<<<aggr_grid, 256>>>(x, agg);
    mlp_tc_kernel<<<mlp_grid, 128, SM_TOT2>>>(agg, buf,
        wh + 0 * 4096, (const float*)d_in[3],
        wh + 1 * 4096, (const float*)d_in[5],
        nullptr, nullptr, 2);

    // Block 1 (2 layers)
    aggregate_kernel<<<aggr_grid, 256>>>(buf, agg);
    mlp_tc_kernel<<<mlp_grid, 128, SM_TOT2>>>(agg, buf,
        wh + 2 * 4096, (const float*)d_in[7],
        wh + 3 * 4096, (const float*)d_in[9],
        nullptr, nullptr, 2);

    // Block 2 + fused final linear (3 layers) -> d_out directly
    aggregate_kernel<<<aggr_grid, 256>>>(buf, agg);
    mlp_tc_kernel<<<mlp_grid, 128, SM_TOT3>>>(agg, (float*)d_out,
        wh + 4 * 4096, (const float*)d_in[11],
        wh + 5 * 4096, (const float*)d_in[13],
        wh + 6 * 4096, (const float*)d_in[15], 3);
}